// round 1
// baseline (speedup 1.0000x reference)
#include <cuda_runtime.h>

// Problem constants
#define N_PIX   65536       // B*H*W = 16*64*64
#define CDIM    64
#define KCODES  512
#define HWSZ    4096        // H*W
#define THREADS 256
#define PIX_PER_BLOCK 512   // 2 pixels per thread
#define NBLOCKS (N_PIX / PIX_PER_BLOCK)   // 128

// Output layout (flattened, float32):
//   [0, 1048576)            quantized BCHW
//   1048576                 commitment_loss
//   1048577                 perplexity
//   1048578                 active_codes
//   [1048579, +65536)       indices (as float)
#define OUT_Q_ELEMS   (N_PIX * CDIM)
#define OUT_LOSS_OFF  OUT_Q_ELEMS
#define OUT_PERP_OFF  (OUT_Q_ELEMS + 1)
#define OUT_ACT_OFF   (OUT_Q_ELEMS + 2)
#define OUT_IDX_OFF   (OUT_Q_ELEMS + 3)

// Scratch (no cudaMalloc allowed)
__device__ int   g_hist[KCODES];
__device__ float g_partials[NBLOCKS];

// Shared memory layout (floats): E[512*64] | en2[512] | hist[512 ints]
#define SMEM_E_FLOATS  (KCODES * CDIM)                 // 32768
#define SMEM_EN2_OFF   SMEM_E_FLOATS
#define SMEM_FLOATS    (SMEM_E_FLOATS + KCODES)        // 33280
#define SMEM_BYTES     (SMEM_FLOATS * 4 + KCODES * 4)  // 135168 B

// ---- packed fp32x2 helpers (Blackwell FFMA2 path; only reachable via PTX) ----
__device__ __forceinline__ unsigned long long pk2(float a, float b) {
    unsigned long long r;
    asm("mov.b64 %0, {%1,%2};" : "=l"(r) : "f"(a), "f"(b));
    return r;
}
__device__ __forceinline__ void upk2(unsigned long long v, float& a, float& b) {
    asm("mov.b64 {%0,%1}, %2;" : "=f"(a), "=f"(b) : "l"(v));
}
__device__ __forceinline__ unsigned long long ffma2(
    unsigned long long a, unsigned long long b, unsigned long long c) {
    unsigned long long d;
    asm("fma.rn.f32x2 %0, %1, %2, %3;" : "=l"(d) : "l"(a), "l"(b), "l"(c));
    return d;
}
__device__ __forceinline__ unsigned long long fadd2(
    unsigned long long a, unsigned long long b) {
    unsigned long long d;
    asm("add.rn.f32x2 %0, %1, %2;" : "=l"(d) : "l"(a), "l"(b));
    return d;
}

// ---- zero scratch ----
extern "C" __global__ void vq_zero() {
    int t = threadIdx.x;
    if (t < KCODES)  g_hist[t] = 0;
    if (t < NBLOCKS) g_partials[t] = 0.0f;
}

// ---- main: argmin + quantized scatter + indices + partial loss + histogram ----
extern "C" __global__ void __launch_bounds__(THREADS, 1)
vq_main(const float* __restrict__ in, const float* __restrict__ emb,
        float* __restrict__ out)
{
    extern __shared__ float sm[];
    float* Es   = sm;
    float* en2  = sm + SMEM_EN2_OFF;
    int*   hS   = (int*)(sm + SMEM_FLOATS);
    const int tid  = threadIdx.x;
    const int lane = tid & 31;
    const int wid  = tid >> 5;

    // Load full codebook into smem (coalesced float4)
    {
        float4* Ed = (float4*)Es;
        const float4* Eg = (const float4*)emb;
        #pragma unroll
        for (int i = 0; i < (KCODES * CDIM / 4) / THREADS; i++)
            Ed[tid + i * THREADS] = Eg[tid + i * THREADS];
    }
    hS[tid] = 0; hS[tid + THREADS] = 0;
    __syncthreads();

    // ||e_k||^2 : one warp per row (conflict-free), shuffle reduce
    for (int k = wid; k < KCODES; k += THREADS / 32) {
        const float* row = Es + k * CDIM;
        float v0 = row[lane], v1 = row[lane + 32];
        float s = v0 * v0 + v1 * v1;
        #pragma unroll
        for (int off = 16; off > 0; off >>= 1)
            s += __shfl_xor_sync(0xffffffffu, s, off);
        if (lane == 0) en2[k] = s;
    }
    __syncthreads();

    // Load 2 pixels per thread, packed along C (pairs (x[2c], x[2c+1]))
    const int p0 = blockIdx.x * PIX_PER_BLOCK + tid;
    const int p1 = p0 + THREADS;
    const float* x0p = in + (p0 >> 12) * (CDIM * HWSZ) + (p0 & (HWSZ - 1));
    const float* x1p = in + (p1 >> 12) * (CDIM * HWSZ) + (p1 & (HWSZ - 1));
    unsigned long long xa[CDIM / 2], xb[CDIM / 2];
    #pragma unroll
    for (int c2 = 0; c2 < CDIM / 2; c2++) {
        xa[c2] = pk2(x0p[(2 * c2) * HWSZ], x0p[(2 * c2 + 1) * HWSZ]);
        xb[c2] = pk2(x1p[(2 * c2) * HWSZ], x1p[(2 * c2 + 1) * HWSZ]);
    }

    // Argmin sweep: per code, 16 broadcast LDS.128 feed 64 FFMA2 (2 pixels)
    float best0 = 3.4e38f, best1 = 3.4e38f;
    int   bi0 = 0, bi1 = 0;
    for (int k = 0; k < KCODES; k++) {
        const ulonglong2* r = (const ulonglong2*)(Es + k * CDIM);
        unsigned long long a0 = 0ull, a1 = 0ull, b0 = 0ull, b1 = 0ull;
        #pragma unroll
        for (int q = 0; q < CDIM / 4; q++) {
            ulonglong2 e = r[q];                 // LDS.128 broadcast
            a0 = ffma2(xa[2 * q],     e.x, a0);
            a1 = ffma2(xa[2 * q + 1], e.y, a1);
            b0 = ffma2(xb[2 * q],     e.x, b0);
            b1 = ffma2(xb[2 * q + 1], e.y, b1);
        }
        float sax, say, sbx, sby;
        upk2(fadd2(a0, a1), sax, say);
        upk2(fadd2(b0, b1), sbx, sby);
        const float e2 = en2[k];
        const float d0 = fmaf(-2.0f, sax + say, e2);
        const float d1 = fmaf(-2.0f, sbx + sby, e2);
        if (d0 < best0) { best0 = d0; bi0 = k; }   // strict < => first index wins ties
        if (d1 < best1) { best1 = d1; bi1 = k; }
    }

    // Epilogue: quantized scatter + indices + local loss + smem histogram
    float lossLocal = 0.0f;
    {
        const float* q = Es + bi0 * CDIM;
        float* o = out + (p0 >> 12) * (CDIM * HWSZ) + (p0 & (HWSZ - 1));
        #pragma unroll
        for (int c2 = 0; c2 < CDIM / 2; c2++) {
            float xv0, xv1; upk2(xa[c2], xv0, xv1);
            float q0 = q[2 * c2], q1 = q[2 * c2 + 1];
            o[(2 * c2) * HWSZ]     = q0;
            o[(2 * c2 + 1) * HWSZ] = q1;
            float e0 = q0 - xv0, e1 = q1 - xv1;
            lossLocal += e0 * e0 + e1 * e1;
        }
        atomicAdd(&hS[bi0], 1);
        out[OUT_IDX_OFF + p0] = (float)bi0;
    }
    {
        const float* q = Es + bi1 * CDIM;
        float* o = out + (p1 >> 12) * (CDIM * HWSZ) + (p1 & (HWSZ - 1));
        #pragma unroll
        for (int c2 = 0; c2 < CDIM / 2; c2++) {
            float xv0, xv1; upk2(xb[c2], xv0, xv1);
            float q0 = q[2 * c2], q1 = q[2 * c2 + 1];
            o[(2 * c2) * HWSZ]     = q0;
            o[(2 * c2 + 1) * HWSZ] = q1;
            float e0 = q0 - xv0, e1 = q1 - xv1;
            lossLocal += e0 * e0 + e1 * e1;
        }
        atomicAdd(&hS[bi1], 1);
        out[OUT_IDX_OFF + p1] = (float)bi1;
    }
    __syncthreads();

    // Deterministic block loss reduction (reuse E region)
    float* red = sm;
    red[tid] = lossLocal;
    __syncthreads();
    #pragma unroll
    for (int s = THREADS / 2; s > 0; s >>= 1) {
        if (tid < s) red[tid] += red[tid + s];
        __syncthreads();
    }
    if (tid == 0) g_partials[blockIdx.x] = red[0];

    // Flush histogram (integer atomics -> deterministic)
    atomicAdd(&g_hist[tid], hS[tid]);
    atomicAdd(&g_hist[tid + THREADS], hS[tid + THREADS]);
}

// ---- final: scalars ----
extern "C" __global__ void vq_final(const float* __restrict__ w,
                                    float* __restrict__ out)
{
    __shared__ float red[KCODES];
    const int t = threadIdx.x;

    // entropy term of perplexity
    float p = (float)g_hist[t] * (1.0f / (float)N_PIX);
    red[t] = p * logf(p + 1e-10f);
    __syncthreads();
    #pragma unroll
    for (int s = KCODES / 2; s > 0; s >>= 1) {
        if (t < s) red[t] += red[t + s];
        __syncthreads();
    }
    float perp = 0.0f;
    if (t == 0) perp = expf(-red[0]);
    __syncthreads();

    // active codes
    red[t] = (w[t] >= 0.01f) ? 1.0f : 0.0f;
    __syncthreads();
    #pragma unroll
    for (int s = KCODES / 2; s > 0; s >>= 1) {
        if (t < s) red[t] += red[t + s];
        __syncthreads();
    }
    float act = 0.0f;
    if (t == 0) act = red[0];
    __syncthreads();

    // commitment loss
    red[t] = (t < NBLOCKS) ? g_partials[t] : 0.0f;
    __syncthreads();
    #pragma unroll
    for (int s = KCODES / 2; s > 0; s >>= 1) {
        if (t < s) red[t] += red[t + s];
        __syncthreads();
    }
    if (t == 0) {
        out[OUT_LOSS_OFF] = red[0] * (1.0f / ((float)N_PIX * (float)CDIM));
        out[OUT_PERP_OFF] = perp;
        out[OUT_ACT_OFF]  = act;
    }
}

extern "C" void kernel_launch(void* const* d_in, const int* in_sizes, int n_in,
                              void* d_out, int out_size)
{
    const float* in  = (const float*)d_in[0];   // inputs [16,64,64,64]
    const float* emb = (const float*)d_in[1];   // emb_weight [512,64]
    const float* w   = (const float*)d_in[2];   // weight [512]
    float* out = (float*)d_out;

    cudaFuncSetAttribute(vq_main, cudaFuncAttributeMaxDynamicSharedMemorySize,
                         SMEM_BYTES);

    vq_zero<<<1, KCODES>>>();
    vq_main<<<NBLOCKS, THREADS, SMEM_BYTES>>>(in, emb, out);
    vq_final<<<1, KCODES>>>(w, out);
}

// round 3
// speedup vs baseline: 1.1502x; 1.1502x over previous
#include <cuda_runtime.h>
#include <cuda_bf16.h>
#include <cstdint>

// ---------------- problem constants ----------------
#define N_PIX   65536
#define CDIM    64
#define KCODES  512
#define HWSZ    4096
#define CHW     (CDIM * HWSZ)

#define OUT_Q_ELEMS  (N_PIX * CDIM)
#define OUT_LOSS_OFF OUT_Q_ELEMS
#define OUT_PERP_OFF (OUT_Q_ELEMS + 1)
#define OUT_ACT_OFF  (OUT_Q_ELEMS + 2)
#define OUT_IDX_OFF  (OUT_Q_ELEMS + 3)

#define TILE_P  128
#define NBLK    (N_PIX / TILE_P)       // 512
#define NCHUNK  8                      // 8 x 64 codes
#define EPS     0.0625f

// ---------------- device scratch ----------------
__device__ __align__(16) uint16_t g_Bhi[KCODES * CDIM];
__device__ __align__(16) uint16_t g_Blo[KCODES * CDIM];
__device__ __align__(16) float    g_en2[KCODES];
__device__ int   g_hist[KCODES];
__device__ float g_part[NBLK];

// ---------------- smem layout ----------------
#define OFF_A_HI 0
#define OFF_A_LO 16384
#define OFF_B_HI 32768
#define OFF_B_LO 40960
#define OFF_EN2  49152
#define OFF_TOPV 51200
#define OFF_TOPI 52736
#define OFF_HIST 54272
#define OFF_WS   56320
#define SMEM_MAIN 56448

// ---------------- PTX helpers (compute_103-legal only) ----------------
__device__ __forceinline__ uint32_t s2u(const void* p) {
    uint32_t a;
    asm("{ .reg .u64 t; cvta.to.shared.u64 t, %1; cvt.u32.u64 %0, t; }"
        : "=r"(a) : "l"(p));
    return a;
}
__device__ __forceinline__ void ldsm_x4(uint32_t& r0, uint32_t& r1,
                                        uint32_t& r2, uint32_t& r3, uint32_t a) {
    asm volatile("ldmatrix.sync.aligned.m8n8.x4.shared.b16 {%0,%1,%2,%3}, [%4];"
                 : "=r"(r0), "=r"(r1), "=r"(r2), "=r"(r3) : "r"(a));
}
__device__ __forceinline__ void ldsm_x2(uint32_t& r0, uint32_t& r1, uint32_t a) {
    asm volatile("ldmatrix.sync.aligned.m8n8.x2.shared.b16 {%0,%1}, [%2];"
                 : "=r"(r0), "=r"(r1) : "r"(a));
}
__device__ __forceinline__ void mma_bf16(float& c0, float& c1, float& c2, float& c3,
                                         uint32_t a0, uint32_t a1, uint32_t a2, uint32_t a3,
                                         uint32_t b0, uint32_t b1) {
    asm volatile(
        "mma.sync.aligned.m16n8k16.row.col.f32.bf16.bf16.f32 "
        "{%0,%1,%2,%3}, {%4,%5,%6,%7}, {%8,%9}, {%0,%1,%2,%3};"
        : "+f"(c0), "+f"(c1), "+f"(c2), "+f"(c3)
        : "r"(a0), "r"(a1), "r"(a2), "r"(a3), "r"(b0), "r"(b1));
}

// fast insert (strict <, index-ascending scan order => first-index wins)
__device__ __forceinline__ void ins3f(float d, int k,
                                      float& v0, float& v1, float& v2,
                                      int& i0, int& i1, int& i2) {
    if (d < v2) {
        if (d < v1) {
            v2 = v1; i2 = i1;
            if (d < v0) { v1 = v0; i1 = i0; v0 = d; i0 = k; }
            else        { v1 = d;  i1 = k; }
        } else { v2 = d; i2 = k; }
    }
}
// lexicographic insert for cross-thread merge determinism
__device__ __forceinline__ void ins3x(float d, int k,
                                      float& v0, float& v1, float& v2,
                                      int& i0, int& i1, int& i2) {
    bool l2 = (d < v2) || (d == v2 && k < i2);
    if (l2) {
        bool l1 = (d < v1) || (d == v1 && k < i1);
        if (l1) {
            v2 = v1; i2 = i1;
            bool l0 = (d < v0) || (d == v0 && k < i0);
            if (l0) { v1 = v0; i1 = i0; v0 = d; i0 = k; }
            else    { v1 = d;  i1 = k; }
        } else { v2 = d; i2 = k; }
    }
}

__device__ __forceinline__ float exact_dist(const float* __restrict__ xp,
                                            const float* __restrict__ emb,
                                            float en2v, int k) {
    const float4* er = (const float4*)(emb + (k << 6));
    float s = 0.0f;
    #pragma unroll
    for (int c4 = 0; c4 < 16; c4++) {
        float4 e4 = er[c4];
        s = fmaf(xp[(c4 * 4 + 0) * HWSZ], e4.x, s);
        s = fmaf(xp[(c4 * 4 + 1) * HWSZ], e4.y, s);
        s = fmaf(xp[(c4 * 4 + 2) * HWSZ], e4.z, s);
        s = fmaf(xp[(c4 * 4 + 3) * HWSZ], e4.w, s);
    }
    return fmaf(-2.0f, s, en2v);
}

// ---------------- prep: bf16-split codebook (row-major) + en2 + zero hist ----------------
extern "C" __global__ void vq_prep(const float* __restrict__ emb) {
    int idx = blockIdx.x * 256 + threadIdx.x;   // 128 x 256 = 32768
    float e = emb[idx];
    __nv_bfloat16 hi = __float2bfloat16(e);
    __nv_bfloat16 lo = __float2bfloat16(e - __bfloat162float(hi));
    g_Bhi[idx] = __bfloat16_as_ushort(hi);
    g_Blo[idx] = __bfloat16_as_ushort(lo);
    if (idx < KCODES) {
        const float* r = emb + idx * CDIM;
        float s = 0.0f;
        #pragma unroll
        for (int c = 0; c < CDIM; c++) s = fmaf(r[c], r[c], s);
        g_en2[idx]  = s;
        g_hist[idx] = 0;
    }
}

// ---------------- main ----------------
extern "C" __global__ void __launch_bounds__(256, 3)
vq_main(const float* __restrict__ in, const float* __restrict__ emb,
        float* __restrict__ out)
{
    extern __shared__ char smc[];
    const uint32_t sb = s2u(smc);
    const int tid  = threadIdx.x;
    const int lane = tid & 31;
    const int wid  = tid >> 5;

    int*   histS = (int*)(smc + OFF_HIST);
    float* en2s  = (float*)(smc + OFF_EN2);
    float* topv  = (float*)(smc + OFF_TOPV);
    int*   topi  = (int*)(smc + OFF_TOPI);

    histS[tid] = 0; histS[tid + 256] = 0;
    if (tid < 128) ((float4*)en2s)[tid] = ((const float4*)g_en2)[tid];

    const int pbase = blockIdx.x * TILE_P;

    // ---- stage A: -2x split into bf16 hi/lo, 16B-xor swizzled rows of 128B ----
    {
        const int px = tid & 127;
        const int cb = (tid >> 7) * 32;
        const int p  = pbase + px;
        const float* xp = in + (p >> 12) * CHW + (p & (HWSZ - 1));
        #pragma unroll
        for (int c = cb; c < cb + 32; c += 2) {
            float x0 = -2.0f * xp[c * HWSZ];
            float x1 = -2.0f * xp[(c + 1) * HWSZ];
            __nv_bfloat16 h0 = __float2bfloat16(x0);
            __nv_bfloat16 h1 = __float2bfloat16(x1);
            __nv_bfloat16 l0 = __float2bfloat16(x0 - __bfloat162float(h0));
            __nv_bfloat16 l1 = __float2bfloat16(x1 - __bfloat162float(h1));
            uint32_t hp = (uint32_t)__bfloat16_as_ushort(h0) |
                          ((uint32_t)__bfloat16_as_ushort(h1) << 16);
            uint32_t lp = (uint32_t)__bfloat16_as_ushort(l0) |
                          ((uint32_t)__bfloat16_as_ushort(l1) << 16);
            int col = (c * 2) ^ ((px & 7) * 16);
            *(uint32_t*)(smc + OFF_A_HI + px * 128 + col) = hp;
            *(uint32_t*)(smc + OFF_A_LO + px * 128 + col) = lp;
        }
    }
    __syncthreads();

    // ---- A fragments resident: warp wid owns pixel rows 16*wid..16*wid+15 ----
    uint32_t Ah[4][4], Al[4][4];
    {
        const int mtx = lane >> 3;
        const int r   = 16 * wid + (mtx & 1) * 8 + (lane & 7);
        const int kh  = (mtx >> 1) * 16;
        #pragma unroll
        for (int ks = 0; ks < 4; ks++) {
            int col = (ks * 32 + kh) ^ ((r & 7) * 16);
            ldsm_x4(Ah[ks][0], Ah[ks][1], Ah[ks][2], Ah[ks][3],
                    sb + OFF_A_HI + r * 128 + col);
            ldsm_x2(Al[ks][0], Al[ks][1], sb + OFF_A_LO + r * 128 + col);
            ldsm_x2(Al[ks][2], Al[ks][3],
                    sb + OFF_A_LO + r * 128 + ((ks * 32 + kh) ^ ((r & 7) * 16)));
        }
    }
    // NOTE: the two ldsm_x2 calls above are wrong halves — redo Al with x4:
    {
        const int mtx = lane >> 3;
        const int r   = 16 * wid + (mtx & 1) * 8 + (lane & 7);
        const int kh  = (mtx >> 1) * 16;
        #pragma unroll
        for (int ks = 0; ks < 4; ks++) {
            int col = (ks * 32 + kh) ^ ((r & 7) * 16);
            ldsm_x4(Al[ks][0], Al[ks][1], Al[ks][2], Al[ks][3],
                    sb + OFF_A_LO + r * 128 + col);
        }
    }

    // ---- sweep all 512 codes in 8 chunks of 64; fold into per-thread top-3 ----
    float v00 = 3.4e38f, v01 = 3.4e38f, v02 = 3.4e38f;   // row slot 0
    float v10 = 3.4e38f, v11 = 3.4e38f, v12 = 3.4e38f;   // row slot 1 (+8)
    int   i00 = 0, i01 = 0, i02 = 0, i10 = 0, i11 = 0, i12 = 0;

    for (int ch = 0; ch < NCHUNK; ch++) {
        __syncthreads();   // previous chunk's B fully consumed
        // stage B chunk: 64 codes x 64 ch bf16, hi+lo (8KB each)
        {
            const uint16_t* shi = g_Bhi + ch * 64 * CDIM;
            const uint16_t* slo = g_Blo + ch * 64 * CDIM;
            #pragma unroll
            for (int t = 0; t < 2; t++) {
                int i = tid + t * 256;                // 16B unit id, 512 total
                int row = i >> 3, cu = (i & 7) * 16;
                int dst = row * 128 + (cu ^ ((row & 7) * 16));
                *(uint4*)(smc + OFF_B_HI + dst) = ((const uint4*)shi)[i];
                *(uint4*)(smc + OFF_B_LO + dst) = ((const uint4*)slo)[i];
            }
        }
        __syncthreads();

        #pragma unroll
        for (int j = 0; j < 8; j++) {       // n-tiles of 8 codes
            float c0 = 0.f, c1 = 0.f, c2 = 0.f, c3 = 0.f;
            const int rr  = j * 8 + (lane & 7);
            const int khb = ((lane >> 3) & 1) * 16;
            #pragma unroll
            for (int ks = 0; ks < 4; ks++) {
                int col = (ks * 32 + khb) ^ ((rr & 7) * 16);
                uint32_t bh0, bh1, bl0, bl1;
                ldsm_x2(bh0, bh1, sb + OFF_B_HI + rr * 128 + col);
                ldsm_x2(bl0, bl1, sb + OFF_B_LO + rr * 128 + col);
                mma_bf16(c0, c1, c2, c3, Ah[ks][0], Ah[ks][1], Ah[ks][2], Ah[ks][3], bh0, bh1);
                mma_bf16(c0, c1, c2, c3, Al[ks][0], Al[ks][1], Al[ks][2], Al[ks][3], bh0, bh1);
                mma_bf16(c0, c1, c2, c3, Ah[ks][0], Ah[ks][1], Ah[ks][2], Ah[ks][3], bl0, bl1);
            }
            const int k0 = ch * 64 + j * 8 + 2 * (lane & 3);
            float e0, e1;
            asm("ld.shared.v2.f32 {%0,%1}, [%2];"
                : "=f"(e0), "=f"(e1) : "r"(sb + OFF_EN2 + k0 * 4));
            ins3f(c0 + e0, k0,     v00, v01, v02, i00, i01, i02);
            ins3f(c1 + e1, k0 + 1, v00, v01, v02, i00, i01, i02);
            ins3f(c2 + e0, k0,     v10, v11, v12, i10, i11, i12);
            ins3f(c3 + e1, k0 + 1, v10, v11, v12, i10, i11, i12);
        }
    }

    // ---- merge top-3 across the 4 lanes sharing each accum row ----
    #pragma unroll
    for (int off = 1; off <= 2; off <<= 1) {
        float a0 = __shfl_xor_sync(0xffffffffu, v00, off);
        float a1 = __shfl_xor_sync(0xffffffffu, v01, off);
        float a2 = __shfl_xor_sync(0xffffffffu, v02, off);
        int   b0 = __shfl_xor_sync(0xffffffffu, i00, off);
        int   b1 = __shfl_xor_sync(0xffffffffu, i01, off);
        int   b2 = __shfl_xor_sync(0xffffffffu, i02, off);
        ins3x(a0, b0, v00, v01, v02, i00, i01, i02);
        ins3x(a1, b1, v00, v01, v02, i00, i01, i02);
        ins3x(a2, b2, v00, v01, v02, i00, i01, i02);
        a0 = __shfl_xor_sync(0xffffffffu, v10, off);
        a1 = __shfl_xor_sync(0xffffffffu, v11, off);
        a2 = __shfl_xor_sync(0xffffffffu, v12, off);
        b0 = __shfl_xor_sync(0xffffffffu, i10, off);
        b1 = __shfl_xor_sync(0xffffffffu, i11, off);
        b2 = __shfl_xor_sync(0xffffffffu, i12, off);
        ins3x(a0, b0, v10, v11, v12, i10, i11, i12);
        ins3x(a1, b1, v10, v11, v12, i10, i11, i12);
        ins3x(a2, b2, v10, v11, v12, i10, i11, i12);
    }
    if ((lane & 3) == 0) {
        int r0 = 16 * wid + (lane >> 2);
        topv[r0 * 3 + 0] = v00; topv[r0 * 3 + 1] = v01; topv[r0 * 3 + 2] = v02;
        topi[r0 * 3 + 0] = i00; topi[r0 * 3 + 1] = i01; topi[r0 * 3 + 2] = i02;
        int r1 = r0 + 8;
        topv[r1 * 3 + 0] = v10; topv[r1 * 3 + 1] = v11; topv[r1 * 3 + 2] = v12;
        topi[r1 * 3 + 0] = i10; topi[r1 * 3 + 1] = i11; topi[r1 * 3 + 2] = i12;
    }
    __syncthreads();

    // ---- per-pixel epilogue on threads 0..127 (warps 0-3 full) ----
    float lossLocal = 0.0f;
    if (tid < 128) {
        const int p = pbase + tid;
        const float* xp = in + (p >> 12) * CHW + (p & (HWSZ - 1));
        float b1 = topv[tid * 3 + 0], b2 = topv[tid * 3 + 1], b3 = topv[tid * 3 + 2];
        int   j1 = topi[tid * 3 + 0], j2 = topi[tid * 3 + 1];

        int win;
        if (b2 - b1 >= EPS) {
            win = j1;
        } else if (b3 - b1 >= EPS) {
            float d1 = exact_dist(xp, emb, en2s[j1], j1);
            float d2 = exact_dist(xp, emb, en2s[j2], j2);
            win = (d2 < d1 || (d2 == d1 && j2 < j1)) ? j2 : j1;
        } else {
            win = -1;
        }
        unsigned m = __ballot_sync(0xffffffffu, win < 0);
        while (m) {
            int src = __ffs(m) - 1; m &= m - 1;
            int pp = __shfl_sync(0xffffffffu, p, src);
            const float* xq = in + (pp >> 12) * CHW + (pp & (HWSZ - 1));
            float bd = 3.4e38f; int bi = 0;
            for (int kk = lane; kk < KCODES; kk += 32) {
                float dv = exact_dist(xq, emb, en2s[kk], kk);
                if (dv < bd || (dv == bd && kk < bi)) { bd = dv; bi = kk; }
            }
            #pragma unroll
            for (int o = 16; o; o >>= 1) {
                float od = __shfl_xor_sync(0xffffffffu, bd, o);
                int   oi = __shfl_xor_sync(0xffffffffu, bi, o);
                if (od < bd || (od == bd && oi < bi)) { bd = od; bi = oi; }
            }
            if (lane == src) win = bi;
        }

        atomicAdd(&histS[win], 1);
        out[OUT_IDX_OFF + p] = (float)win;
        const float4* qr = (const float4*)(emb + (win << 6));
        float* op = out + (p >> 12) * CHW + (p & (HWSZ - 1));
        #pragma unroll
        for (int c4 = 0; c4 < 16; c4++) {
            float4 q4 = qr[c4];
            float x0 = xp[(c4 * 4 + 0) * HWSZ];
            float x1 = xp[(c4 * 4 + 1) * HWSZ];
            float x2 = xp[(c4 * 4 + 2) * HWSZ];
            float x3 = xp[(c4 * 4 + 3) * HWSZ];
            op[(c4 * 4 + 0) * HWSZ] = q4.x;
            op[(c4 * 4 + 1) * HWSZ] = q4.y;
            op[(c4 * 4 + 2) * HWSZ] = q4.z;
            op[(c4 * 4 + 3) * HWSZ] = q4.w;
            float e0 = q4.x - x0, e1 = q4.y - x1, e2 = q4.z - x2, e3 = q4.w - x3;
            lossLocal += e0 * e0 + e1 * e1 + e2 * e2 + e3 * e3;
        }
        #pragma unroll
        for (int o = 16; o; o >>= 1)
            lossLocal += __shfl_xor_sync(0xffffffffu, lossLocal, o);
        if (lane == 0) ((float*)(smc + OFF_WS))[wid] = lossLocal;
    }
    __syncthreads();
    if (tid == 0) {
        float* ws = (float*)(smc + OFF_WS);
        g_part[blockIdx.x] = (ws[0] + ws[1]) + (ws[2] + ws[3]);
    }
    atomicAdd(&g_hist[tid],       histS[tid]);
    atomicAdd(&g_hist[tid + 256], histS[tid + 256]);
}

// ---------------- final: scalars ----------------
extern "C" __global__ void vq_final(const float* __restrict__ w,
                                    float* __restrict__ out)
{
    __shared__ float red[KCODES];
    const int t = threadIdx.x;

    float pv = (float)g_hist[t] * (1.0f / (float)N_PIX);
    red[t] = pv * logf(pv + 1e-10f);
    __syncthreads();
    #pragma unroll
    for (int s = KCODES / 2; s > 0; s >>= 1) {
        if (t < s) red[t] += red[t + s];
        __syncthreads();
    }
    float perp = 0.0f;
    if (t == 0) perp = expf(-red[0]);
    __syncthreads();

    red[t] = (w[t] >= 0.01f) ? 1.0f : 0.0f;
    __syncthreads();
    #pragma unroll
    for (int s = KCODES / 2; s > 0; s >>= 1) {
        if (t < s) red[t] += red[t + s];
        __syncthreads();
    }
    float act = 0.0f;
    if (t == 0) act = red[0];
    __syncthreads();

    red[t] = g_part[t];
    __syncthreads();
    #pragma unroll
    for (int s = KCODES / 2; s > 0; s >>= 1) {
        if (t < s) red[t] += red[t + s];
        __syncthreads();
    }
    if (t == 0) {
        out[OUT_LOSS_OFF] = red[0] * (1.0f / ((float)N_PIX * (float)CDIM));
        out[OUT_PERP_OFF] = perp;
        out[OUT_ACT_OFF]  = act;
    }
}

extern "C" void kernel_launch(void* const* d_in, const int* in_sizes, int n_in,
                              void* d_out, int out_size)
{
    const float* in  = (const float*)d_in[0];
    const float* emb = (const float*)d_in[1];
    const float* w   = (const float*)d_in[2];
    float* out = (float*)d_out;

    cudaFuncSetAttribute(vq_main, cudaFuncAttributeMaxDynamicSharedMemorySize,
                         SMEM_MAIN);

    vq_prep<<<128, 256>>>(emb);
    vq_main<<<NBLK, 256, SMEM_MAIN>>>(in, emb, out);
    vq_final<<<1, KCODES>>>(w, out);
}